// round 13
// baseline (speedup 1.0000x reference)
#include <cuda_runtime.h>
#include <cuda_fp16.h>
#include <cstdint>
#include <cstddef>

#define B_ 4
#define S_ 4096
#define D_ 768
#define ATTN_SCALE 0.03608439182435161f   // 1/sqrt(768)
#define EXP_SHIFT 4.0f                    // P=exp(logit-4): fp16-safe; cancels in P/rowsum

// ---------------- scratch (device globals: allocation-free rule) -----------
__device__ __half g_xh[(size_t)B_ * S_ * D_];
__device__ __half g_Wvh[(size_t)D_ * D_];        // fp16 Wv (K-major [e][d])
__device__ __half g_WqT[(size_t)D_ * D_];        // fp16 Wq^T [d][e]
__device__ __half g_WkT[(size_t)D_ * D_];        // fp16 Wk^T [d][e]
__device__ float  g_Mf [(size_t)D_ * D_];        // fp32 M^T accumulator
__device__ __half g_Mt [(size_t)D_ * D_];        // M^T: g_Mt[d'][d] = sum_e Wq[e,d]Wk[e,d']
__device__ __half g_Gh [(size_t)B_ * S_ * D_];   // G = x*M
__device__ __half g_Vth[(size_t)B_ * D_ * S_];   // V transposed: [b][e][s]
__device__ __half g_Ph [(size_t)B_ * S_ * S_];   // exp(logit-4), fp16
__device__ float  g_rowsum[B_ * S_];

// ---------------- helpers ----------------------------------------------------
static __device__ __forceinline__ uint32_t smem_u32(const void* p){
    uint32_t a;
    asm("{ .reg .u64 t; cvta.to.shared.u64 t, %1; cvt.u32.u64 %0, t; }" : "=r"(a) : "l"(p));
    return a;
}

static __device__ __forceinline__ uint32_t pack2(float a, float b){
    __half2 h = __floats2half2_rn(a, b);
    return *reinterpret_cast<uint32_t*>(&h);
}

static __device__ __forceinline__ void cp16(uint32_t sa, const void* g){
    asm volatile("cp.async.ca.shared.global [%0], [%1], 16;" :: "r"(sa), "l"(g));
}
#define CP_COMMIT() asm volatile("cp.async.commit_group;" ::: "memory")
#define CP_WAIT2()  asm volatile("cp.async.wait_group 2;"  ::: "memory")

// stage (uint32 view): A[128 rows][20 u32] then B[128][20] (16 u32 = 32 fp16 + pad 4)
#define ROWU   20
#define BOFFU  2560                  // 128*20
#define SSTGU  5120                  // u32 per stage
#define SMEM_BYTES (4 * SSTGU * 4)   // 4 stages = 81920 B -> 2 CTAs/SM

// 128 threads: each loads 4x16B per operand per stage
static __device__ __forceinline__ void stage_load(uint32_t sbase,
        const __half* __restrict__ A, const __half* __restrict__ Bm,
        int rsA, int rsB, int tid){
    #pragma unroll
    for (int i = 0; i < 4; i++){
        const int idx = tid + 128*i;          // 512 x 16B per operand
        const int r = idx >> 2, c = idx & 3;
        cp16(sbase + (uint32_t)(r*ROWU + c*4)*4u,           A  + (size_t)r*rsA + c*8);
        cp16(sbase + (uint32_t)(BOFFU + r*ROWU + c*4)*4u,   Bm + (size_t)r*rsB + c*8);
    }
}

static __device__ __forceinline__ void mma16(float* d, const uint32_t* a, const uint32_t* b){
    asm volatile("mma.sync.aligned.m16n8k16.row.col.f32.f16.f16.f32 "
        "{%0,%1,%2,%3}, {%4,%5,%6,%7}, {%8,%9}, {%0,%1,%2,%3};"
        : "+f"(d[0]), "+f"(d[1]), "+f"(d[2]), "+f"(d[3])
        : "r"(a[0]), "r"(a[1]), "r"(a[2]), "r"(a[3]), "r"(b[0]), "r"(b[1]));
}

// warp tile 64(m) x 64(n), k-chunk 32 (2 ksteps of 16); 4 warps = 2m x 2n
static __device__ __forceinline__ void compute_chunk(float acc[4][8][4],
        const uint32_t* __restrict__ st, int WM, int WN, int lane){
    const uint32_t* sA = st;
    const uint32_t* sB = st + BOFFU;
    #pragma unroll
    for (int s = 0; s < 2; s++){
        const int c0 = s*8 + (lane & 3);
        uint32_t a[4][4], b[8][2];
        #pragma unroll
        for (int f = 0; f < 4; f++){
            const uint32_t* p = sA + (WM + 16*f + (lane >> 2))*ROWU + c0;
            a[f][0] = p[0];
            a[f][1] = p[8*ROWU];
            a[f][2] = p[4];
            a[f][3] = p[8*ROWU + 4];
        }
        #pragma unroll
        for (int g = 0; g < 8; g++){
            const uint32_t* p = sB + (WN + 8*g + (lane >> 2))*ROWU + c0;
            b[g][0] = p[0];
            b[g][1] = p[4];
        }
        #pragma unroll
        for (int f = 0; f < 4; f++)
            #pragma unroll
            for (int g = 0; g < 8; g++)
                mma16(acc[f][g], a[f], b[g]);
    }
}

// 4-stage cp.async software pipeline over nch k-chunks of 32
static __device__ __forceinline__ void gemm_pipeline(float acc[4][8][4], uint32_t* smu,
        const __half* __restrict__ A, const __half* __restrict__ Bm,
        int rsA, int rsB, int nch, int tid, int WM, int WN, int lane){
    const uint32_t sb = smem_u32(smu);
    #pragma unroll
    for (int p = 0; p < 3; p++){
        if (p < nch) stage_load(sb + (uint32_t)(p*SSTGU*4), A + p*32, Bm + p*32, rsA, rsB, tid);
        CP_COMMIT();
    }
    #pragma unroll 1
    for (int ch = 0; ch < nch; ch++){
        CP_WAIT2();
        __syncthreads();
        const int nx = ch + 3;
        if (nx < nch)
            stage_load(sb + (uint32_t)((nx & 3)*SSTGU*4), A + (size_t)nx*32, Bm + (size_t)nx*32, rsA, rsB, tid);
        CP_COMMIT();
        compute_chunk(acc, smu + (ch & 3)*SSTGU, WM, WN, lane);
    }
}

#define ACC_INIT(acc) \
    _Pragma("unroll") for (int f_ = 0; f_ < 4; f_++) \
    _Pragma("unroll") for (int g_ = 0; g_ < 8; g_++) \
    _Pragma("unroll") for (int j_ = 0; j_ < 4; j_++) acc[f_][g_][j_] = 0.0f;

// ---------------- prep kernels -----------------------------------------------
// convert x -> fp16; also zero rowsums (x/scores stream)
__global__ void k_cvt_x(const float* __restrict__ x){
    const int gid = blockIdx.x * 256 + threadIdx.x;
    if (gid < B_ * S_) g_rowsum[gid] = 0.0f;
    const size_t i = (size_t)gid * 8;
    const float4 u = *reinterpret_cast<const float4*>(x + i);
    const float4 v = *reinterpret_cast<const float4*>(x + i + 4);
    uint4 o = make_uint4(pack2(u.x,u.y), pack2(u.z,u.w), pack2(v.x,v.y), pack2(v.z,v.w));
    *reinterpret_cast<uint4*>(g_xh + i) = o;
}

// convert Wv -> fp16; also zero g_Mf (weight stream, before k_M)
__global__ void k_cvt_wv(const float* __restrict__ Wv){
    const int gid = blockIdx.x * 256 + threadIdx.x;
    const size_t i = (size_t)gid * 8;
    #pragma unroll
    for (int j = 0; j < 8; j++) g_Mf[i + j] = 0.0f;
    const float4 u = *reinterpret_cast<const float4*>(Wv + i);
    const float4 v = *reinterpret_cast<const float4*>(Wv + i + 4);
    uint4 o = make_uint4(pack2(u.x,u.y), pack2(u.z,u.w), pack2(v.x,v.y), pack2(v.z,v.w));
    *reinterpret_cast<uint4*>(g_Wvh + i) = o;
}

// transpose+convert Wq, Wk: [e][d] fp32 -> [d][e] fp16. grid (24,24,2), 256 thr
__global__ void k_trW(const float* __restrict__ Wq, const float* __restrict__ Wk){
    __shared__ float t[32][33];
    const float* src = blockIdx.z ? Wk : Wq;
    __half* dst = blockIdx.z ? g_WkT : g_WqT;
    const int bx = blockIdx.x * 32, by = blockIdx.y * 32;  // bx: d, by: e
    const int tx = threadIdx.x & 31, ty = threadIdx.x >> 5;
    #pragma unroll
    for (int i = 0; i < 32; i += 8)
        t[ty + i][tx] = src[(size_t)(by + ty + i) * D_ + bx + tx];   // t[e][d]
    __syncthreads();
    #pragma unroll
    for (int i = 0; i < 32; i += 8)
        dst[(size_t)(bx + ty + i) * D_ + by + tx] = __float2half(t[tx][ty + i]);
}

// ---------------- kernel M: Mf[d'][d] += partial over k-slice ----------------
// grid(6 mt, 6 nt, 4 kslice); each does 128x128x192
__global__ void __launch_bounds__(128,2)
k_M(){
    extern __shared__ __align__(16) uint32_t smu[];
    const int tid = threadIdx.x, lane = tid & 31, wid = tid >> 5;
    const int WM = (wid & 1) * 64, WN = (wid >> 1) * 64;
    const int mt = blockIdx.x, nt = blockIdx.y, ksl = blockIdx.z;

    const __half* A  = g_WqT + (size_t)mt * 128 * D_ + ksl * 192;
    const __half* Bm = g_WkT + (size_t)nt * 128 * D_ + ksl * 192;

    float acc[4][8][4];
    ACC_INIT(acc);
    gemm_pipeline(acc, smu, A, Bm, D_, D_, 6, tid, WM, WN, lane);

    #pragma unroll
    for (int f = 0; f < 4; f++){
        const int m0 = mt*128 + WM + 16*f + (lane >> 2);
        #pragma unroll
        for (int g = 0; g < 8; g++){
            const int n0 = nt*128 + WN + 8*g + 2*(lane & 3);
            atomicAdd(&g_Mf[(size_t)(n0  )*D_ + m0    ], acc[f][g][0]);
            atomicAdd(&g_Mf[(size_t)(n0+1)*D_ + m0    ], acc[f][g][1]);
            atomicAdd(&g_Mf[(size_t)(n0  )*D_ + m0 + 8], acc[f][g][2]);
            atomicAdd(&g_Mf[(size_t)(n0+1)*D_ + m0 + 8], acc[f][g][3]);
        }
    }
}

// vectorized fp32 -> fp16 convert of M (8 elems/thread)
__global__ void k_Mred(){
    const size_t i = (size_t)(blockIdx.x * 256 + threadIdx.x) * 8;
    const float4 u = *reinterpret_cast<const float4*>(g_Mf + i);
    const float4 v = *reinterpret_cast<const float4*>(g_Mf + i + 4);
    uint4 o = make_uint4(pack2(u.x,u.y), pack2(u.z,u.w), pack2(v.x,v.y), pack2(v.z,v.w));
    *reinterpret_cast<uint4*>(g_Mt + i) = o;
}

// ---------------- kernel G: G = x*M ------------------------------------------
// grid(128 row-tiles, 6 col-tiles); 128 threads, 4 warps 64x64
__global__ void __launch_bounds__(128,2)
k_g(){
    extern __shared__ __align__(16) uint32_t smu[];
    const int tid = threadIdx.x, lane = tid & 31, wid = tid >> 5;
    const int WM = (wid & 1) * 64, WN = (wid >> 1) * 64;
    const int rt = blockIdx.x, ct = blockIdx.y;

    const __half* A  = g_xh + (size_t)rt * 128 * D_;
    const __half* Bm = g_Mt + (size_t)ct * 128 * D_;

    float acc[4][8][4];
    ACC_INIT(acc);
    gemm_pipeline(acc, smu, A, Bm, D_, D_, 24, tid, WM, WN, lane);

    __half* dst = g_Gh + (size_t)rt * 128 * D_ + ct * 128;
    #pragma unroll
    for (int f = 0; f < 4; f++){
        const int m0 = WM + 16*f + (lane >> 2);
        #pragma unroll
        for (int g = 0; g < 8; g++){
            const int n0 = WN + 8*g + 2*(lane & 3);
            *reinterpret_cast<uint32_t*>(dst + (size_t)m0*D_ + n0)     = pack2(acc[f][g][0], acc[f][g][1]);
            *reinterpret_cast<uint32_t*>(dst + (size_t)(m0+8)*D_ + n0) = pack2(acc[f][g][2], acc[f][g][3]);
        }
    }
}

// ---------------- merged kernel: V (768 CTAs) + causal scores (2112 CTAs) ----
// All CTAs do 24 k-chunks -> uniform work -> one packed wave schedule.
__global__ void __launch_bounds__(128,2)
k_sv(){
    extern __shared__ __align__(16) uint32_t smu[];
    const int tid = threadIdx.x, lane = tid & 31, wid = tid >> 5;
    const int WM = (wid & 1) * 64, WN = (wid >> 1) * 64;
    const int bid = blockIdx.x;

    if (bid < 768){
        // ---- V tile: V = x*Wv^T, stored transposed ----
        const int rt = bid & 127, ct = bid >> 7;       // 128 rt x 6 ct
        const __half* A  = g_xh  + (size_t)rt * 128 * D_;
        const __half* Bm = g_Wvh + (size_t)ct * 128 * D_;

        float acc[4][8][4];
        ACC_INIT(acc);
        gemm_pipeline(acc, smu, A, Bm, D_, D_, 24, tid, WM, WN, lane);

        __syncthreads();
        float* sT = reinterpret_cast<float*>(smu);   // [128 n][stride 132 m]
        #pragma unroll
        for (int f = 0; f < 4; f++){
            const int m0 = WM + 16*f + (lane >> 2);
            #pragma unroll
            for (int g = 0; g < 8; g++){
                const int n0 = WN + 8*g + 2*(lane & 3);
                sT[(n0  )*132 + m0    ] = acc[f][g][0];
                sT[(n0+1)*132 + m0    ] = acc[f][g][1];
                sT[(n0  )*132 + m0 + 8] = acc[f][g][2];
                sT[(n0+1)*132 + m0 + 8] = acc[f][g][3];
            }
        }
        __syncthreads();
        const int b = (rt * 128) >> 12;
        const int srow = (rt * 128) & 4095;
        const int e = tid;
        __half* dst = g_Vth + ((size_t)b*D_ + ct*128 + e) * S_ + srow;
        const float* src = sT + e*132;
        #pragma unroll
        for (int i = 0; i < 16; i++){
            const float4 u = *reinterpret_cast<const float4*>(src + 8*i);
            const float4 v = *reinterpret_cast<const float4*>(src + 8*i + 4);
            uint4 o = make_uint4(pack2(u.x,u.y), pack2(u.z,u.w), pack2(v.x,v.y), pack2(v.z,v.w));
            *reinterpret_cast<uint4*>(dst + 8*i) = o;
        }
    } else {
        // ---- scores tile: S = G x^T -> fp16 exp(logit-4), rowsum atomics ----
        const int sid = bid - 768;
        const int b = sid / 528, p = sid % 528;
        int qt = (int)((sqrtf(8.0f*(float)p + 1.0f) - 1.0f) * 0.5f);
        while ((qt+1)*(qt+2)/2 <= p) qt++;
        while (qt*(qt+1)/2 > p) qt--;
        const int kt = p - qt*(qt+1)/2;

        const __half* A  = g_Gh + ((size_t)b*S_ + qt*128) * D_;
        const __half* Bm = g_xh + ((size_t)b*S_ + kt*128) * D_;

        float acc[4][8][4];
        ACC_INIT(acc);
        gemm_pipeline(acc, smu, A, Bm, D_, D_, 24, tid, WM, WN, lane);

        __half* Pb = g_Ph + ((size_t)b*S_ + qt*128) * S_ + kt*128;
        const bool diag = (kt == qt);

        #pragma unroll
        for (int f = 0; f < 4; f++){
            const int m0 = WM + 16*f + (lane >> 2);
            float s0 = 0.0f, s1 = 0.0f;
            #pragma unroll
            for (int g = 0; g < 8; g++){
                const int n0 = WN + 8*g + 2*(lane & 3);
                float e00 = __expf(fmaf(acc[f][g][0], ATTN_SCALE, -EXP_SHIFT));
                float e01 = __expf(fmaf(acc[f][g][1], ATTN_SCALE, -EXP_SHIFT));
                float e10 = __expf(fmaf(acc[f][g][2], ATTN_SCALE, -EXP_SHIFT));
                float e11 = __expf(fmaf(acc[f][g][3], ATTN_SCALE, -EXP_SHIFT));
                if (diag){
                    if (n0     > m0    ) e00 = 0.0f;
                    if (n0 + 1 > m0    ) e01 = 0.0f;
                    if (n0     > m0 + 8) e10 = 0.0f;
                    if (n0 + 1 > m0 + 8) e11 = 0.0f;
                }
                const __half2 h0 = __floats2half2_rn(e00, e01);
                const __half2 h1 = __floats2half2_rn(e10, e11);
                s0 += __low2float(h0) + __high2float(h0);
                s1 += __low2float(h1) + __high2float(h1);
                *reinterpret_cast<__half2*>(Pb + (size_t)m0*S_ + n0)     = h0;
                *reinterpret_cast<__half2*>(Pb + (size_t)(m0+8)*S_ + n0) = h1;
            }
            s0 += __shfl_xor_sync(0xffffffffu, s0, 1);
            s0 += __shfl_xor_sync(0xffffffffu, s0, 2);
            s1 += __shfl_xor_sync(0xffffffffu, s1, 1);
            s1 += __shfl_xor_sync(0xffffffffu, s1, 2);
            if ((lane & 3) == 0){
                atomicAdd(&g_rowsum[b*S_ + qt*128 + m0],     s0);
                atomicAdd(&g_rowsum[b*S_ + qt*128 + m0 + 8], s1);
            }
        }
    }
}

// ---------------- kernel 3: O = (P @ Vt^T) / rowsum --------------------------
// 1D grid of 768: qt-descending outer (LPT), (b, e-tile) inner
__global__ void __launch_bounds__(128,2)
k_pv(float* __restrict__ out){
    extern __shared__ __align__(16) uint32_t smu[];
    const int tid = threadIdx.x, lane = tid & 31, wid = tid >> 5;
    const int WM = (wid & 1) * 64, WN = (wid >> 1) * 64;
    const int bid = blockIdx.x;
    const int qt = 31 - bid / 24;
    const int sub = bid % 24;
    const int b = sub / 6, ex = sub % 6;

    const __half* A  = g_Ph  + ((size_t)b*S_ + qt*128) * S_;
    const __half* Bm = g_Vth + ((size_t)b*D_ + ex*128) * S_;
    const int nch = (qt + 1) * 4;

    float acc[4][8][4];
    ACC_INIT(acc);
    gemm_pipeline(acc, smu, A, Bm, S_, S_, nch, tid, WM, WN, lane);

    #pragma unroll
    for (int f = 0; f < 4; f++){
        const int m0 = WM + 16*f + (lane >> 2);
        const float inv0 = 1.0f / g_rowsum[b*S_ + qt*128 + m0];
        const float inv1 = 1.0f / g_rowsum[b*S_ + qt*128 + m0 + 8];
        float* dst0 = out + ((size_t)b*S_ + qt*128 + m0    ) * D_ + ex*128;
        float* dst1 = out + ((size_t)b*S_ + qt*128 + m0 + 8) * D_ + ex*128;
        #pragma unroll
        for (int g = 0; g < 8; g++){
            const int n0 = WN + 8*g + 2*(lane & 3);
            *reinterpret_cast<float2*>(dst0 + n0) =
                make_float2(acc[f][g][0]*inv0, acc[f][g][1]*inv0);
            *reinterpret_cast<float2*>(dst1 + n0) =
                make_float2(acc[f][g][2]*inv1, acc[f][g][3]*inv1);
        }
    }
}

// ---------------- launcher ---------------------------------------------------
// Two-stream DAG:
//   s0: cvt_x --------------[wait eW] k_g -> k_sv (V + scores) -> k_pv
//   s2: [wait e0] cvt_wv -> trW -> k_M -> k_Mred (rec eW)
extern "C" void kernel_launch(void* const* d_in, const int* in_sizes, int n_in,
                              void* d_out, int out_size)
{
    (void)in_sizes; (void)n_in; (void)out_size;
    const float* x  = (const float*)d_in[0];
    const float* Wq = (const float*)d_in[1];
    const float* Wk = (const float*)d_in[2];
    const float* Wv = (const float*)d_in[3];
    float* out = (float*)d_out;

    static cudaStream_t s2 = nullptr;
    static cudaEvent_t e0, eW;
    if (!s2){
        cudaStreamCreateWithFlags(&s2, cudaStreamNonBlocking);
        cudaEventCreateWithFlags(&e0, cudaEventDisableTiming);
        cudaEventCreateWithFlags(&eW, cudaEventDisableTiming);
        cudaFuncSetAttribute(k_M,   cudaFuncAttributeMaxDynamicSharedMemorySize, SMEM_BYTES);
        cudaFuncSetAttribute(k_g,   cudaFuncAttributeMaxDynamicSharedMemorySize, SMEM_BYTES);
        cudaFuncSetAttribute(k_sv,  cudaFuncAttributeMaxDynamicSharedMemorySize, SMEM_BYTES);
        cudaFuncSetAttribute(k_pv,  cudaFuncAttributeMaxDynamicSharedMemorySize, SMEM_BYTES);
    }

    // fork side stream off stream 0
    cudaEventRecord(e0, 0);
    cudaStreamWaitEvent(s2, e0, 0);

    // weight path on s2 (k_cvt_wv also zeroes g_Mf)
    k_cvt_wv<<<288, 256, 0, s2>>>(Wv);
    k_trW   <<<dim3(24, 24, 2), 256, 0, s2>>>(Wq, Wk);
    k_M     <<<dim3(6, 6, 4), 128, SMEM_BYTES, s2>>>();
    k_Mred  <<<288, 256, 0, s2>>>();
    cudaEventRecord(eW, s2);

    // x path on stream 0 (also zeroes rowsums)
    k_cvt_x<<<6144, 256>>>(x);

    // join, then G -> (V + scores merged) -> PV, all on stream 0
    cudaStreamWaitEvent(0, eW, 0);
    k_g <<<dim3(128, 6), 128, SMEM_BYTES>>>();
    k_sv<<<2880, 128, SMEM_BYTES>>>();
    k_pv<<<768, 128, SMEM_BYTES>>>(out);
}

// round 14
// speedup vs baseline: 1.5949x; 1.5949x over previous
#include <cuda_runtime.h>
#include <cuda_fp16.h>
#include <cstdint>
#include <cstddef>

#define B_ 4
#define S_ 4096
#define D_ 768
#define ATTN_SCALE 0.03608439182435161f   // 1/sqrt(768)
#define EXP_SHIFT 4.0f                    // P=exp(logit-4): fp16-safe; cancels in P/rowsum

// ---------------- scratch (device globals: allocation-free rule) -----------
__device__ __half g_xh[(size_t)B_ * S_ * D_];
__device__ __half g_Wvh[(size_t)D_ * D_];        // fp16 Wv (K-major [e][d])
__device__ __half g_WqT[(size_t)D_ * D_];        // fp16 Wq^T [d][e]
__device__ __half g_WkT[(size_t)D_ * D_];        // fp16 Wk^T [d][e]
__device__ float  g_Mf [(size_t)D_ * D_];        // fp32 M^T accumulator
__device__ __half g_Mt [(size_t)D_ * D_];        // M^T: g_Mt[d'][d] = sum_e Wq[e,d]Wk[e,d']
__device__ __half g_Gh [(size_t)B_ * S_ * D_];   // G = x*M
__device__ __half g_Vth[(size_t)B_ * D_ * S_];   // V transposed: [b][e][s]
__device__ __half g_Ph [(size_t)B_ * S_ * S_];   // exp(logit-4), fp16
__device__ float  g_rowsum[B_ * S_];

// ---------------- helpers ----------------------------------------------------
static __device__ __forceinline__ uint32_t smem_u32(const void* p){
    uint32_t a;
    asm("{ .reg .u64 t; cvta.to.shared.u64 t, %1; cvt.u32.u64 %0, t; }" : "=r"(a) : "l"(p));
    return a;
}

static __device__ __forceinline__ uint32_t pack2(float a, float b){
    __half2 h = __floats2half2_rn(a, b);
    return *reinterpret_cast<uint32_t*>(&h);
}

static __device__ __forceinline__ void cp16(uint32_t sa, const void* g){
    asm volatile("cp.async.ca.shared.global [%0], [%1], 16;" :: "r"(sa), "l"(g));
}
#define CP_COMMIT() asm volatile("cp.async.commit_group;" ::: "memory")
#define CP_WAIT2()  asm volatile("cp.async.wait_group 2;"  ::: "memory")

// stage (uint32 view): A[128 rows][20 u32] then B[128][20] (16 u32 = 32 fp16 + pad 4)
#define ROWU   20
#define BOFFU  2560                  // 128*20
#define SSTGU  5120                  // u32 per stage
#define SMEM_BYTES (4 * SSTGU * 4)   // 4 stages = 81920 B -> 2 CTAs/SM

// 128 threads: each loads 4x16B per operand per stage
static __device__ __forceinline__ void stage_load(uint32_t sbase,
        const __half* __restrict__ A, const __half* __restrict__ Bm,
        int rsA, int rsB, int tid){
    #pragma unroll
    for (int i = 0; i < 4; i++){
        const int idx = tid + 128*i;          // 512 x 16B per operand
        const int r = idx >> 2, c = idx & 3;
        cp16(sbase + (uint32_t)(r*ROWU + c*4)*4u,           A  + (size_t)r*rsA + c*8);
        cp16(sbase + (uint32_t)(BOFFU + r*ROWU + c*4)*4u,   Bm + (size_t)r*rsB + c*8);
    }
}

static __device__ __forceinline__ void mma16(float* d, const uint32_t* a, const uint32_t* b){
    asm volatile("mma.sync.aligned.m16n8k16.row.col.f32.f16.f16.f32 "
        "{%0,%1,%2,%3}, {%4,%5,%6,%7}, {%8,%9}, {%0,%1,%2,%3};"
        : "+f"(d[0]), "+f"(d[1]), "+f"(d[2]), "+f"(d[3])
        : "r"(a[0]), "r"(a[1]), "r"(a[2]), "r"(a[3]), "r"(b[0]), "r"(b[1]));
}

// warp tile 64(m) x 64(n), k-chunk 32 (2 ksteps of 16); 4 warps = 2m x 2n
static __device__ __forceinline__ void compute_chunk(float acc[4][8][4],
        const uint32_t* __restrict__ st, int WM, int WN, int lane){
    const uint32_t* sA = st;
    const uint32_t* sB = st + BOFFU;
    #pragma unroll
    for (int s = 0; s < 2; s++){
        const int c0 = s*8 + (lane & 3);
        uint32_t a[4][4], b[8][2];
        #pragma unroll
        for (int f = 0; f < 4; f++){
            const uint32_t* p = sA + (WM + 16*f + (lane >> 2))*ROWU + c0;
            a[f][0] = p[0];
            a[f][1] = p[8*ROWU];
            a[f][2] = p[4];
            a[f][3] = p[8*ROWU + 4];
        }
        #pragma unroll
        for (int g = 0; g < 8; g++){
            const uint32_t* p = sB + (WN + 8*g + (lane >> 2))*ROWU + c0;
            b[g][0] = p[0];
            b[g][1] = p[4];
        }
        #pragma unroll
        for (int f = 0; f < 4; f++)
            #pragma unroll
            for (int g = 0; g < 8; g++)
                mma16(acc[f][g], a[f], b[g]);
    }
}

// 4-stage cp.async software pipeline over nch k-chunks of 32
static __device__ __forceinline__ void gemm_pipeline(float acc[4][8][4], uint32_t* smu,
        const __half* __restrict__ A, const __half* __restrict__ Bm,
        int rsA, int rsB, int nch, int tid, int WM, int WN, int lane){
    const uint32_t sb = smem_u32(smu);
    #pragma unroll
    for (int p = 0; p < 3; p++){
        if (p < nch) stage_load(sb + (uint32_t)(p*SSTGU*4), A + p*32, Bm + p*32, rsA, rsB, tid);
        CP_COMMIT();
    }
    #pragma unroll 1
    for (int ch = 0; ch < nch; ch++){
        CP_WAIT2();
        __syncthreads();
        const int nx = ch + 3;
        if (nx < nch)
            stage_load(sb + (uint32_t)((nx & 3)*SSTGU*4), A + (size_t)nx*32, Bm + (size_t)nx*32, rsA, rsB, tid);
        CP_COMMIT();
        compute_chunk(acc, smu + (ch & 3)*SSTGU, WM, WN, lane);
    }
}

#define ACC_INIT(acc) \
    _Pragma("unroll") for (int f_ = 0; f_ < 4; f_++) \
    _Pragma("unroll") for (int g_ = 0; g_ < 8; g_++) \
    _Pragma("unroll") for (int j_ = 0; j_ < 4; j_++) acc[f_][g_][j_] = 0.0f;

// ---------------- prep kernels -----------------------------------------------
// convert x -> fp16; also zero rowsums (x/scores stream)
__global__ void k_cvt_x(const float* __restrict__ x){
    const int gid = blockIdx.x * 256 + threadIdx.x;
    if (gid < B_ * S_) g_rowsum[gid] = 0.0f;
    const size_t i = (size_t)gid * 8;
    const float4 u = *reinterpret_cast<const float4*>(x + i);
    const float4 v = *reinterpret_cast<const float4*>(x + i + 4);
    uint4 o = make_uint4(pack2(u.x,u.y), pack2(u.z,u.w), pack2(v.x,v.y), pack2(v.z,v.w));
    *reinterpret_cast<uint4*>(g_xh + i) = o;
}

// convert Wv -> fp16; also zero g_Mf (weight stream, before k_M)
__global__ void k_cvt_wv(const float* __restrict__ Wv){
    const int gid = blockIdx.x * 256 + threadIdx.x;
    const size_t i = (size_t)gid * 8;
    #pragma unroll
    for (int j = 0; j < 8; j++) g_Mf[i + j] = 0.0f;
    const float4 u = *reinterpret_cast<const float4*>(Wv + i);
    const float4 v = *reinterpret_cast<const float4*>(Wv + i + 4);
    uint4 o = make_uint4(pack2(u.x,u.y), pack2(u.z,u.w), pack2(v.x,v.y), pack2(v.z,v.w));
    *reinterpret_cast<uint4*>(g_Wvh + i) = o;
}

// transpose+convert Wq, Wk: [e][d] fp32 -> [d][e] fp16. grid (24,24,2), 256 thr
__global__ void k_trW(const float* __restrict__ Wq, const float* __restrict__ Wk){
    __shared__ float t[32][33];
    const float* src = blockIdx.z ? Wk : Wq;
    __half* dst = blockIdx.z ? g_WkT : g_WqT;
    const int bx = blockIdx.x * 32, by = blockIdx.y * 32;  // bx: d, by: e
    const int tx = threadIdx.x & 31, ty = threadIdx.x >> 5;
    #pragma unroll
    for (int i = 0; i < 32; i += 8)
        t[ty + i][tx] = src[(size_t)(by + ty + i) * D_ + bx + tx];   // t[e][d]
    __syncthreads();
    #pragma unroll
    for (int i = 0; i < 32; i += 8)
        dst[(size_t)(bx + ty + i) * D_ + by + tx] = __float2half(t[tx][ty + i]);
}

// ---------------- kernel M: Mf[d'][d] += partial over k-slice ----------------
// grid(6 mt, 6 nt, 4 kslice); each does 128x128x192
__global__ void __launch_bounds__(128,2)
k_M(){
    extern __shared__ __align__(16) uint32_t smu[];
    const int tid = threadIdx.x, lane = tid & 31, wid = tid >> 5;
    const int WM = (wid & 1) * 64, WN = (wid >> 1) * 64;
    const int mt = blockIdx.x, nt = blockIdx.y, ksl = blockIdx.z;

    const __half* A  = g_WqT + (size_t)mt * 128 * D_ + ksl * 192;
    const __half* Bm = g_WkT + (size_t)nt * 128 * D_ + ksl * 192;

    float acc[4][8][4];
    ACC_INIT(acc);
    gemm_pipeline(acc, smu, A, Bm, D_, D_, 6, tid, WM, WN, lane);

    #pragma unroll
    for (int f = 0; f < 4; f++){
        const int m0 = mt*128 + WM + 16*f + (lane >> 2);
        #pragma unroll
        for (int g = 0; g < 8; g++){
            const int n0 = nt*128 + WN + 8*g + 2*(lane & 3);
            atomicAdd(&g_Mf[(size_t)(n0  )*D_ + m0    ], acc[f][g][0]);
            atomicAdd(&g_Mf[(size_t)(n0+1)*D_ + m0    ], acc[f][g][1]);
            atomicAdd(&g_Mf[(size_t)(n0  )*D_ + m0 + 8], acc[f][g][2]);
            atomicAdd(&g_Mf[(size_t)(n0+1)*D_ + m0 + 8], acc[f][g][3]);
        }
    }
}

// vectorized fp32 -> fp16 convert of M (8 elems/thread)
__global__ void k_Mred(){
    const size_t i = (size_t)(blockIdx.x * 256 + threadIdx.x) * 8;
    const float4 u = *reinterpret_cast<const float4*>(g_Mf + i);
    const float4 v = *reinterpret_cast<const float4*>(g_Mf + i + 4);
    uint4 o = make_uint4(pack2(u.x,u.y), pack2(u.z,u.w), pack2(v.x,v.y), pack2(v.z,v.w));
    *reinterpret_cast<uint4*>(g_Mt + i) = o;
}

// ---------------- kernel G: G = x*M ------------------------------------------
// grid(128 row-tiles, 6 col-tiles); 128 threads, 4 warps 64x64
__global__ void __launch_bounds__(128,2)
k_g(){
    extern __shared__ __align__(16) uint32_t smu[];
    const int tid = threadIdx.x, lane = tid & 31, wid = tid >> 5;
    const int WM = (wid & 1) * 64, WN = (wid >> 1) * 64;
    const int rt = blockIdx.x, ct = blockIdx.y;

    const __half* A  = g_xh + (size_t)rt * 128 * D_;
    const __half* Bm = g_Mt + (size_t)ct * 128 * D_;

    float acc[4][8][4];
    ACC_INIT(acc);
    gemm_pipeline(acc, smu, A, Bm, D_, D_, 24, tid, WM, WN, lane);

    __half* dst = g_Gh + (size_t)rt * 128 * D_ + ct * 128;
    #pragma unroll
    for (int f = 0; f < 4; f++){
        const int m0 = WM + 16*f + (lane >> 2);
        #pragma unroll
        for (int g = 0; g < 8; g++){
            const int n0 = WN + 8*g + 2*(lane & 3);
            *reinterpret_cast<uint32_t*>(dst + (size_t)m0*D_ + n0)     = pack2(acc[f][g][0], acc[f][g][1]);
            *reinterpret_cast<uint32_t*>(dst + (size_t)(m0+8)*D_ + n0) = pack2(acc[f][g][2], acc[f][g][3]);
        }
    }
}

// ---------------- kernel V: V = x*Wv^T, stored transposed --------------------
__global__ void __launch_bounds__(128,2)
k_v(){
    extern __shared__ __align__(16) uint32_t smu[];
    const int tid = threadIdx.x, lane = tid & 31, wid = tid >> 5;
    const int WM = (wid & 1) * 64, WN = (wid >> 1) * 64;
    const int rt = blockIdx.x, ct = blockIdx.y;

    const __half* A  = g_xh  + (size_t)rt * 128 * D_;
    const __half* Bm = g_Wvh + (size_t)ct * 128 * D_;

    float acc[4][8][4];
    ACC_INIT(acc);
    gemm_pipeline(acc, smu, A, Bm, D_, D_, 24, tid, WM, WN, lane);

    // transpose through smem (fp32), convert + write coalesced columns of g_Vth
    __syncthreads();
    float* sT = reinterpret_cast<float*>(smu);   // [128 n][stride 132 m] = 67584 B
    #pragma unroll
    for (int f = 0; f < 4; f++){
        const int m0 = WM + 16*f + (lane >> 2);
        #pragma unroll
        for (int g = 0; g < 8; g++){
            const int n0 = WN + 8*g + 2*(lane & 3);
            sT[(n0  )*132 + m0    ] = acc[f][g][0];
            sT[(n0+1)*132 + m0    ] = acc[f][g][1];
            sT[(n0  )*132 + m0 + 8] = acc[f][g][2];
            sT[(n0+1)*132 + m0 + 8] = acc[f][g][3];
        }
    }
    __syncthreads();
    const int b = (rt * 128) >> 12;
    const int srow = (rt * 128) & 4095;
    const int e = tid;
    __half* dst = g_Vth + ((size_t)b*D_ + ct*128 + e) * S_ + srow;
    const float* src = sT + e*132;
    #pragma unroll
    for (int i = 0; i < 16; i++){
        const float4 u = *reinterpret_cast<const float4*>(src + 8*i);
        const float4 v = *reinterpret_cast<const float4*>(src + 8*i + 4);
        uint4 o = make_uint4(pack2(u.x,u.y), pack2(u.z,u.w), pack2(v.x,v.y), pack2(v.z,v.w));
        *reinterpret_cast<uint4*>(dst + 8*i) = o;
    }
}

// ---------------- kernel 2: causal scores = G x^T -> fp16 exp(logit-4) -------
// grid(528 causal tile-pairs, 4 batches)
__global__ void __launch_bounds__(128,2)
k_scores(){
    extern __shared__ __align__(16) uint32_t smu[];
    const int tid = threadIdx.x, lane = tid & 31, wid = tid >> 5;
    const int WM = (wid & 1) * 64, WN = (wid >> 1) * 64;
    const int b = blockIdx.y;
    const int p = blockIdx.x;
    int qt = (int)((sqrtf(8.0f*(float)p + 1.0f) - 1.0f) * 0.5f);
    while ((qt+1)*(qt+2)/2 <= p) qt++;
    while (qt*(qt+1)/2 > p) qt--;
    const int kt = p - qt*(qt+1)/2;

    const __half* A  = g_Gh + ((size_t)b*S_ + qt*128) * D_;
    const __half* Bm = g_xh + ((size_t)b*S_ + kt*128) * D_;

    float acc[4][8][4];
    ACC_INIT(acc);
    gemm_pipeline(acc, smu, A, Bm, D_, D_, 24, tid, WM, WN, lane);

    __half* Pb = g_Ph + ((size_t)b*S_ + qt*128) * S_ + kt*128;
    const bool diag = (kt == qt);

    #pragma unroll
    for (int f = 0; f < 4; f++){
        const int m0 = WM + 16*f + (lane >> 2);
        float s0 = 0.0f, s1 = 0.0f;
        #pragma unroll
        for (int g = 0; g < 8; g++){
            const int n0 = WN + 8*g + 2*(lane & 3);
            float e00 = __expf(fmaf(acc[f][g][0], ATTN_SCALE, -EXP_SHIFT));
            float e01 = __expf(fmaf(acc[f][g][1], ATTN_SCALE, -EXP_SHIFT));
            float e10 = __expf(fmaf(acc[f][g][2], ATTN_SCALE, -EXP_SHIFT));
            float e11 = __expf(fmaf(acc[f][g][3], ATTN_SCALE, -EXP_SHIFT));
            if (diag){
                if (n0     > m0    ) e00 = 0.0f;
                if (n0 + 1 > m0    ) e01 = 0.0f;
                if (n0     > m0 + 8) e10 = 0.0f;
                if (n0 + 1 > m0 + 8) e11 = 0.0f;
            }
            const __half2 h0 = __floats2half2_rn(e00, e01);
            const __half2 h1 = __floats2half2_rn(e10, e11);
            s0 += __low2float(h0) + __high2float(h0);
            s1 += __low2float(h1) + __high2float(h1);
            *reinterpret_cast<__half2*>(Pb + (size_t)m0*S_ + n0)     = h0;
            *reinterpret_cast<__half2*>(Pb + (size_t)(m0+8)*S_ + n0) = h1;
        }
        s0 += __shfl_xor_sync(0xffffffffu, s0, 1);
        s0 += __shfl_xor_sync(0xffffffffu, s0, 2);
        s1 += __shfl_xor_sync(0xffffffffu, s1, 1);
        s1 += __shfl_xor_sync(0xffffffffu, s1, 2);
        if ((lane & 3) == 0){
            atomicAdd(&g_rowsum[b*S_ + qt*128 + m0],     s0);
            atomicAdd(&g_rowsum[b*S_ + qt*128 + m0 + 8], s1);
        }
    }
}

// ---------------- kernel 3: O = (P @ Vt^T) / rowsum --------------------------
// 1D grid of 768: qt-descending outer (LPT), (b, e-tile) inner
__global__ void __launch_bounds__(128,2)
k_pv(float* __restrict__ out){
    extern __shared__ __align__(16) uint32_t smu[];
    const int tid = threadIdx.x, lane = tid & 31, wid = tid >> 5;
    const int WM = (wid & 1) * 64, WN = (wid >> 1) * 64;
    const int bid = blockIdx.x;
    const int qt = 31 - bid / 24;
    const int sub = bid % 24;
    const int b = sub / 6, ex = sub % 6;

    const __half* A  = g_Ph  + ((size_t)b*S_ + qt*128) * S_;
    const __half* Bm = g_Vth + ((size_t)b*D_ + ex*128) * S_;
    const int nch = (qt + 1) * 4;

    float acc[4][8][4];
    ACC_INIT(acc);
    gemm_pipeline(acc, smu, A, Bm, S_, S_, nch, tid, WM, WN, lane);

    #pragma unroll
    for (int f = 0; f < 4; f++){
        const int m0 = WM + 16*f + (lane >> 2);
        const float inv0 = 1.0f / g_rowsum[b*S_ + qt*128 + m0];
        const float inv1 = 1.0f / g_rowsum[b*S_ + qt*128 + m0 + 8];
        float* dst0 = out + ((size_t)b*S_ + qt*128 + m0    ) * D_ + ex*128;
        float* dst1 = out + ((size_t)b*S_ + qt*128 + m0 + 8) * D_ + ex*128;
        #pragma unroll
        for (int g = 0; g < 8; g++){
            const int n0 = WN + 8*g + 2*(lane & 3);
            *reinterpret_cast<float2*>(dst0 + n0) =
                make_float2(acc[f][g][0]*inv0, acc[f][g][1]*inv0);
            *reinterpret_cast<float2*>(dst1 + n0) =
                make_float2(acc[f][g][2]*inv1, acc[f][g][3]*inv1);
        }
    }
}

// ---------------- launcher ---------------------------------------------------
// Two-stream DAG (capture-legal fork/join via events):
//   stream0: cvt_x ---------------------[wait eW] k_g -> k_scores [wait eV] k_pv
//   s2:      [wait e0] cvt_wv -> trW -> k_M -> k_Mred [wait eX] k_v (rec eV)
extern "C" void kernel_launch(void* const* d_in, const int* in_sizes, int n_in,
                              void* d_out, int out_size)
{
    (void)in_sizes; (void)n_in; (void)out_size;
    const float* x  = (const float*)d_in[0];
    const float* Wq = (const float*)d_in[1];
    const float* Wk = (const float*)d_in[2];
    const float* Wv = (const float*)d_in[3];
    float* out = (float*)d_out;

    static cudaStream_t s2 = nullptr;
    static cudaEvent_t e0, eX, eW, eV;
    if (!s2){
        cudaStreamCreateWithFlags(&s2, cudaStreamNonBlocking);
        cudaEventCreateWithFlags(&e0, cudaEventDisableTiming);
        cudaEventCreateWithFlags(&eX, cudaEventDisableTiming);
        cudaEventCreateWithFlags(&eW, cudaEventDisableTiming);
        cudaEventCreateWithFlags(&eV, cudaEventDisableTiming);
        cudaFuncSetAttribute(k_M,      cudaFuncAttributeMaxDynamicSharedMemorySize, SMEM_BYTES);
        cudaFuncSetAttribute(k_g,      cudaFuncAttributeMaxDynamicSharedMemorySize, SMEM_BYTES);
        cudaFuncSetAttribute(k_v,      cudaFuncAttributeMaxDynamicSharedMemorySize, SMEM_BYTES);
        cudaFuncSetAttribute(k_scores, cudaFuncAttributeMaxDynamicSharedMemorySize, SMEM_BYTES);
        cudaFuncSetAttribute(k_pv,     cudaFuncAttributeMaxDynamicSharedMemorySize, SMEM_BYTES);
    }

    // fork side stream off stream 0
    cudaEventRecord(e0, 0);
    cudaStreamWaitEvent(s2, e0, 0);

    // weight path on s2 (also zeroes g_Mf inside k_cvt_wv)
    k_cvt_wv<<<288, 256, 0, s2>>>(Wv);
    k_trW   <<<dim3(24, 24, 2), 256, 0, s2>>>(Wq, Wk);
    k_M     <<<dim3(6, 6, 4), 128, SMEM_BYTES, s2>>>();
    k_Mred  <<<288, 256, 0, s2>>>();
    cudaEventRecord(eW, s2);

    // x path on stream 0 (also zeroes rowsums)
    k_cvt_x<<<6144, 256>>>(x);
    cudaEventRecord(eX, 0);

    // V on s2: needs x (eX) and Wvh (s2 order)
    cudaStreamWaitEvent(s2, eX, 0);
    k_v<<<dim3(128, 6), 128, SMEM_BYTES, s2>>>();
    cudaEventRecord(eV, s2);

    // G -> scores on stream 0: needs Mt (eW) and x (order)
    cudaStreamWaitEvent(0, eW, 0);
    k_g     <<<dim3(128, 6), 128, SMEM_BYTES>>>();
    k_scores<<<dim3(528, 4), 128, SMEM_BYTES>>>();

    // PV: needs scores (order) and V (eV)
    cudaStreamWaitEvent(0, eV, 0);
    k_pv<<<768, 128, SMEM_BYTES>>>(out);
}